// round 13
// baseline (speedup 1.0000x reference)
#include <cuda_runtime.h>
#include <cuda_fp16.h>
#include <cstdint>

// Geometry (fixed): B=2, C0=256, D=64, H=64, W=16
#define D_   64
#define H_   64
#define W_   16
#define DHW_ 65536
#define DP_  66
#define HP_  66
#define WP_  18
#define PPOS_ (DP_*HP_*WP_)        // 78408 padded positions per batch

// ---------------------------------------------------------------------------
// Device scratch (zero-initialized at load; halos never written -> stay zero)
// ---------------------------------------------------------------------------
__device__ __half g_p1h[2 * PPOS_ * 256];       // conv1 input
__device__ __half g_p2h[2 * PPOS_ * 256];       // conv1 out / conv2 in
__device__ __half g_p3h[2 * PPOS_ * 64];        // conv2 out / conv3 in
__device__ float  g_f3 [2 * DHW_ * 32];
__device__ __half g_w1t[108 * 256 * 64];        // pre-swizzled hi-only tiles
__device__ __half g_w2t[108 * 64  * 64];
__device__ __half g_w3t[ 27 * 32  * 64];
__device__ float  g_bn [2 * (256 + 64 + 32)];

#define SWZ128(o) ((o) ^ (((o) >> 3) & 0x70))

__device__ __forceinline__ uint32_t smem_to_u32(const void* p) {
    uint32_t a;
    asm("{ .reg .u64 t; cvta.to.shared.u64 t, %1; cvt.u32.u64 %0, t; }" : "=r"(a) : "l"(p));
    return a;
}
__device__ __forceinline__ void ldm_x4(uint32_t* r, uint32_t addr) {
    asm volatile("ldmatrix.sync.aligned.m8n8.x4.shared.b16 {%0,%1,%2,%3}, [%4];"
                 : "=r"(r[0]), "=r"(r[1]), "=r"(r[2]), "=r"(r[3]) : "r"(addr));
}
__device__ __forceinline__ void mma16816(float* c, const uint32_t* a, const uint32_t* b) {
    asm volatile("mma.sync.aligned.m16n8k16.row.col.f32.f16.f16.f32 "
                 "{%0,%1,%2,%3}, {%4,%5,%6,%7}, {%8,%9}, {%0,%1,%2,%3};"
                 : "+f"(c[0]), "+f"(c[1]), "+f"(c[2]), "+f"(c[3])
                 : "r"(a[0]), "r"(a[1]), "r"(a[2]), "r"(a[3]), "r"(b[0]), "r"(b[1]));
}
__device__ __forceinline__ void cpasync16(uint32_t dst, const void* src) {
    asm volatile("cp.async.cg.shared.global [%0], [%1], 16;" :: "r"(dst), "l"(src));
}
#define CP_COMMIT() asm volatile("cp.async.commit_group;" ::: "memory")
#define CP_WAIT0()  asm volatile("cp.async.wait_group 0;" ::: "memory")

// ---------------------------------------------------------------------------
// fea (NCDHW fp32) -> padded channels-last fp16 (transpose in smem),
// packed 2-channel (u32) stores
// ---------------------------------------------------------------------------
__global__ void convert_input(const float* __restrict__ fea,
                              __half* __restrict__ ph) {
    __shared__ float tile[64][65];
    int pos0 = blockIdx.x * 64;
    int cb   = blockIdx.y * 64;
    int b    = blockIdx.z;
    int x = threadIdx.x & 63, y = threadIdx.x >> 6;
    const float* src = fea + (size_t)b * 256 * DHW_;
    #pragma unroll
    for (int r = 0; r < 64; r += 4)
        tile[r + y][x] = src[(size_t)(cb + r + y) * DHW_ + pos0 + x];
    __syncthreads();
    #pragma unroll
    for (int i = threadIdx.x; i < 64 * 32; i += 256) {
        int p  = i >> 5;
        int cp = i & 31;
        int pos = pos0 + p;
        int d = pos >> 10, h = (pos >> 4) & 63, w = pos & 15;
        size_t pa = ((((size_t)b * DP_ + d + 1) * HP_ + h + 1) * WP_ + w + 1) * 256 + cb + cp * 2;
        __half h0 = __float2half_rn(tile[cp * 2 + 0][p]);
        __half h1 = __float2half_rn(tile[cp * 2 + 1][p]);
        *(uint32_t*)(ph + pa) =
            (uint32_t)__half_as_ushort(h0) | ((uint32_t)__half_as_ushort(h1) << 16);
    }
}

// ---------------------------------------------------------------------------
// Weight prep (all three layers, one launch): fp32 -> pre-swizzled SW128
// K-major fp16 tiles, hi-only, layout [iter][COUT*64]
// ---------------------------------------------------------------------------
__device__ __forceinline__ void prep_one(const float* __restrict__ Wsrc,
                                         __half* __restrict__ out,
                                         int idx, int CIN, int COUT) {
    int it = idx / (COUT * 64);
    int r  = idx % (COUT * 64);
    int co = r / 64, kk = r % 64;
    int ch = CIN / 64;
    int t  = it / ch, cc = it % ch;
    int ci = cc * 64 + kk;
    float v = Wsrc[((size_t)co * CIN + ci) * 27 + t];
    int so = SWZ128(co * 128 + kk * 2);
    out[(size_t)it * (COUT * 64) + so / 2] = __float2half_rn(v);
}
__global__ void prep_all(const float* __restrict__ W1, const float* __restrict__ W2,
                         const float* __restrict__ W3,
                         __half* __restrict__ w1t, __half* __restrict__ w2t,
                         __half* __restrict__ w3t) {
    const int E1 = 108 * 256 * 64, E2 = 108 * 64 * 64, E3 = 27 * 32 * 64;
    int idx = blockIdx.x * blockDim.x + threadIdx.x;
    if (idx < E1) prep_one(W1, w1t, idx, 256, 256);
    else if (idx < E1 + E2) prep_one(W2, w2t, idx - E1, 256, 64);
    else if (idx < E1 + E2 + E3) prep_one(W3, w3t, idx - E1 - E2, 64, 32);
}

// ---------------------------------------------------------------------------
// Fold BN params for all three conv layers
// ---------------------------------------------------------------------------
__global__ void bn_fold(const float* g1, const float* b1, const float* m1, const float* v1,
                        const float* g2, const float* b2, const float* m2, const float* v2,
                        const float* g3, const float* b3, const float* m3, const float* v3) {
    int t = threadIdx.x;
    if (t < 256) {
        float sc = g1[t] * rsqrtf(v1[t] + 1e-5f);
        g_bn[t] = sc; g_bn[256 + t] = b1[t] - m1[t] * sc;
    } else if (t < 320) {
        int c = t - 256;
        float sc = g2[c] * rsqrtf(v2[c] + 1e-5f);
        g_bn[512 + c] = sc; g_bn[576 + c] = b2[c] - m2[c] * sc;
    } else if (t < 352) {
        int c = t - 320;
        float sc = g3[c] * rsqrtf(v3[c] + 1e-5f);
        g_bn[640 + c] = sc; g_bn[672 + c] = b3[c] - m3[c] * sc;
    }
}

// ---------------------------------------------------------------------------
// HMMA implicit-GEMM conv, R11-proven pipeline:
//  - A halo double-buffered across phases (prefetched at m9 in {5,6})
//  - B quad-buffered, two taps per commit, CP_WAIT0 + barrier per 2 taps
//  - prefetch distance 2 taps: in-flight writes never touch slots being read
//  - NT may be odd (conv3: 27): last pair computes a single tap
// MINB=1 instantiations get the full 255-register budget (1 CTA/SM).
// ---------------------------------------------------------------------------
template<int CIN, int COUTF, int NLOC, int MTILE, int MWARPS, int NWARPS,
         bool F32OUT, int MINB>
__global__ __launch_bounds__(256, MINB)
void conv_mma(const __half* __restrict__ pin_h,
              const __half* __restrict__ wt,
              const float* __restrict__ scv, const float* __restrict__ shv,
              __half* __restrict__ pout_h,
              float* __restrict__ foutp) {
    extern __shared__ __align__(1024) char smem[];
    constexpr int CHUNKS  = CIN / 64;
    constexpr int NPH     = 3 * CHUNKS;
    constexpr int NT      = NPH * 9;
    constexpr int HROWS   = MTILE / 16;
    constexpr int HT      = 64 / HROWS;
    constexpr int AROWS   = (HROWS + 2) * 18;
    constexpr int ASZ     = ((AROWS * 128 + 1023) / 1024) * 1024;
    constexpr int AOFF    = 2048;
    constexpr int BBASE   = AOFF + 2 * ASZ;
    constexpr int BSTRIDE = NLOC * 128;
    constexpr int WM = MTILE / MWARPS;
    constexpr int WN = NLOC / NWARPS;
    constexpr int MTI = WM / 16;
    constexpr int NTI = WN / 8;

    const uint32_t sbase = smem_to_u32(smem);
    const int tid = threadIdx.x, wid = tid >> 5, l = tid & 31;
    const int ntile = blockIdx.x / HT;
    const int h0 = (blockIdx.x % HT) * HROWS;
    const int d  = blockIdx.y;
    const int b  = blockIdx.z;
    const int n0 = ntile * NLOC;
    const int wm = wid % MWARPS, wn = wid / MWARPS;
    float* scp = (float*)smem;

    for (int c = tid; c < NLOC; c += 256) {
        scp[c] = scv[n0 + c];
        scp[NLOC + c] = shv[n0 + c];
    }

    float acc[MTI][NTI][4];
    #pragma unroll
    for (int i = 0; i < MTI; i++)
        #pragma unroll
        for (int j = 0; j < NTI; j++)
            #pragma unroll
            for (int q = 0; q < 4; q++) acc[i][j][q] = 0.f;

    const int arow = ((l >> 3) & 1) * 8 + (l & 7);
    const int akh  = (l >> 4);
    const int brow = (l >> 4) * 8 + (l & 7);
    const int bkh  = (l >> 3) & 1;
    const int mbase = wm * WM + arow;
    const int mh0 = mbase >> 4;
    const int mw  = mbase & 15;

    auto stageA = [&](int p2) {
        const int kd2 = p2 / CHUNKS, cc2 = p2 % CHUNKS;
        const size_t gb = (((size_t)b * DP_ + d + kd2) * HP_ + h0) * WP_;
        const uint32_t abuf = sbase + AOFF + (p2 & 1) * ASZ;
        #pragma unroll 1
        for (int i = tid; i < AROWS * 8; i += 256) {
            int r = i >> 3, c8 = i & 7;
            int hz = r / 18, wz = r - hz * 18;
            size_t ga = (gb + (size_t)hz * WP_ + wz) * CIN + cc2 * 64 + c8 * 8;
            cpasync16(abuf + SWZ128(r * 128 + c8 * 16), pin_h + ga);
        }
    };
    auto stageB = [&](int gt2) {
        const int p2 = gt2 / 9, tp2 = gt2 - p2 * 9;
        const int kd2 = p2 / CHUNKS, cc2 = p2 % CHUNKS;
        const int iter = (kd2 * 9 + tp2) * CHUNKS + cc2;
        const char* whi = (const char*)(wt + (size_t)iter * (COUTF * 64) + n0 * 64);
        const uint32_t dst = sbase + BBASE + (gt2 & 3) * BSTRIDE;
        #pragma unroll 1
        for (int i = tid; i < NLOC * 8; i += 256)
            cpasync16(dst + i * 16, whi + i * 16);
    };

    // prologue: A(0) + B taps 0,1
    stageA(0);
    stageB(0);
    stageB(1);
    CP_COMMIT();

    #pragma unroll 1
    for (int gs = 0; gs < (NT + 1) / 2; ++gs) {
        const int gt0 = 2 * gs;
        CP_WAIT0();
        __syncthreads();
        // prefetch next pair of B taps + (conditionally) next phase's A
        if (gt0 + 2 < NT) stageB(gt0 + 2);
        if (gt0 + 3 < NT) stageB(gt0 + 3);
        {
            const int m9 = gt0 % 9, ph0 = gt0 / 9;
            if ((m9 == 5 || m9 == 6) && ph0 + 1 < NPH) stageA(ph0 + 1);
        }
        CP_COMMIT();

        #pragma unroll
        for (int t2 = 0; t2 < 2; ++t2) {
            const int gt = gt0 + t2;
            if (t2 == 1 && gt >= NT) break;    // odd-NT tail: single tap
            const int phs = gt / 9, tap = gt - phs * 9;
            const uint32_t abase = sbase + AOFF + (phs & 1) * ASZ;
            const uint32_t bbuf  = sbase + BBASE + (gt & 3) * BSTRIDE;
            const int kh = tap / 3, kw = tap - kh * 3;
            const int rb = (mh0 + kh) * 18 + mw + kw;

            #pragma unroll
            for (int ks = 0; ks < 4; ks++) {
                uint32_t ah[MTI][4];
                #pragma unroll
                for (int i = 0; i < MTI; i++) {
                    uint32_t so = SWZ128((uint32_t)(rb + i * 18) * 128 + (ks * 2 + akh) * 16);
                    ldm_x4(ah[i], abase + so);
                }
                uint32_t bh[NTI / 2][4];
                #pragma unroll
                for (int jp = 0; jp < NTI / 2; jp++) {
                    uint32_t so = SWZ128((uint32_t)(wn * WN + jp * 16 + brow) * 128 + (ks * 2 + bkh) * 16);
                    ldm_x4(bh[jp], bbuf + so);
                }
                #pragma unroll
                for (int i = 0; i < MTI; i++)
                    #pragma unroll
                    for (int jp = 0; jp < NTI / 2; jp++) {
                        mma16816(acc[i][2*jp],   ah[i], &bh[jp][0]);
                        mma16816(acc[i][2*jp+1], ah[i], &bh[jp][2]);
                    }
            }
        }
    }

    // ---- epilogue: BN + LeakyReLU, write channels-last ----
    #pragma unroll
    for (int i = 0; i < MTI; i++) {
        #pragma unroll
        for (int j = 0; j < NTI; j++) {
            int nl = wn * WN + j * 8 + (l & 3) * 2;
            int co = n0 + nl;
            float s0 = scp[nl],     h0c = scp[NLOC + nl];
            float s1 = scp[nl + 1], h1c = scp[NLOC + nl + 1];
            #pragma unroll
            for (int rh = 0; rh < 2; rh++) {
                int m  = wm * WM + i * 16 + (l >> 2) + rh * 8;
                int hh = h0 + (m >> 4), ww = m & 15;
                float y0 = acc[i][j][rh * 2 + 0] * s0 + h0c;
                float y1 = acc[i][j][rh * 2 + 1] * s1 + h1c;
                y0 = (y0 > 0.f) ? y0 : 0.01f * y0;
                y1 = (y1 > 0.f) ? y1 : 0.01f * y1;
                if (F32OUT) {
                    float* op = foutp + ((((size_t)b * D_ + d) * H_ + hh) * W_ + ww) * COUTF + co;
                    op[0] = y0; op[1] = y1;
                } else {
                    __half h0b = __float2half_rn(y0);
                    __half h1b = __float2half_rn(y1);
                    size_t pa = ((((size_t)b * DP_ + d + 1) * HP_ + hh + 1) * WP_ + ww + 1) * COUTF + co;
                    *(uint32_t*)(pout_h + pa) =
                        (uint32_t)__half_as_ushort(h0b) | ((uint32_t)__half_as_ushort(h1b) << 16);
                }
            }
        }
    }
}

// ---------------------------------------------------------------------------
// Gather (channels-last, 128B/point) + MLP 35->32 (BN,ReLU) -> 3
// ---------------------------------------------------------------------------
__global__ void gather_mlp(const float* __restrict__ f3,
                           const int* __restrict__ grid_ind,
                           const float* __restrict__ xyz,
                           const float* __restrict__ Wo1, const float* __restrict__ bo1,
                           const float* __restrict__ go,  const float* __restrict__ bo,
                           const float* __restrict__ mo,  const float* __restrict__ vo,
                           const float* __restrict__ Wo2, const float* __restrict__ bo2,
                           float* __restrict__ out, int N) {
    __shared__ float sW1[35 * 32];
    __shared__ float sb1[32], ssc[32], ssh[32];
    __shared__ float sW2[32 * 3], sb2[3];
    const int tid = threadIdx.x;
    for (int i = tid; i < 35 * 32; i += blockDim.x) sW1[i] = Wo1[i];
    if (tid < 32) {
        float sc = go[tid] * rsqrtf(vo[tid] + 1e-5f);
        ssc[tid] = sc;
        ssh[tid] = bo[tid] - mo[tid] * sc;
        sb1[tid] = bo1[tid];
    }
    for (int i = tid; i < 96; i += blockDim.x) sW2[i] = Wo2[i];
    if (tid < 3) sb2[tid] = bo2[tid];
    __syncthreads();

    int idx = blockIdx.x * blockDim.x + tid;
    if (idx >= 2 * N) return;
    int b = idx / N;
    const int* gi = grid_ind + (size_t)idx * 3;
    int sp = (gi[0] * H_ + gi[1]) * W_ + gi[2];

    float xin[35];
    const float* fb = f3 + ((size_t)b * DHW_ + sp) * 32;
    #pragma unroll
    for (int c = 0; c < 32; c++) xin[c] = fb[c];
    const float* xp = xyz + (size_t)idx * 3;
    xin[32] = xp[0]; xin[33] = xp[1]; xin[34] = xp[2];

    float hreg[32];
    #pragma unroll
    for (int j = 0; j < 32; j++) hreg[j] = sb1[j];
    #pragma unroll 5
    for (int k = 0; k < 35; k++) {
        float xk = xin[k];
        #pragma unroll
        for (int j = 0; j < 32; j++) hreg[j] = fmaf(xk, sW1[k * 32 + j], hreg[j]);
    }
    #pragma unroll
    for (int j = 0; j < 32; j++) {
        float y = hreg[j] * ssc[j] + ssh[j];
        hreg[j] = (y > 0.f) ? y : 0.f;
    }
    float o0 = sb2[0], o1 = sb2[1], o2 = sb2[2];
    #pragma unroll
    for (int j = 0; j < 32; j++) {
        o0 = fmaf(hreg[j], sW2[j * 3 + 0], o0);
        o1 = fmaf(hreg[j], sW2[j * 3 + 1], o1);
        o2 = fmaf(hreg[j], sW2[j * 3 + 2], o2);
    }
    float* op = out + (size_t)idx * 3;
    op[0] = o0; op[1] = o1; op[2] = o2;
}

extern "C" void kernel_launch(void* const* d_in, const int* in_sizes, int n_in,
                              void* d_out, int out_size) {
    const float* fea      = (const float*)d_in[0];
    const int*   grid_ind = (const int*)  d_in[1];
    const float* xyz      = (const float*)d_in[2];
    const float* W1 = (const float*)d_in[3];
    const float *g1 = (const float*)d_in[4], *b1 = (const float*)d_in[5];
    const float *m1 = (const float*)d_in[6], *v1 = (const float*)d_in[7];
    const float* W2 = (const float*)d_in[8];
    const float *g2 = (const float*)d_in[9],  *b2 = (const float*)d_in[10];
    const float *m2 = (const float*)d_in[11], *v2 = (const float*)d_in[12];
    const float* W3 = (const float*)d_in[13];
    const float *g3 = (const float*)d_in[14], *b3 = (const float*)d_in[15];
    const float *m3 = (const float*)d_in[16], *v3 = (const float*)d_in[17];
    const float* Wo1 = (const float*)d_in[18];
    const float* bo1 = (const float*)d_in[19];
    const float *go = (const float*)d_in[20], *bo = (const float*)d_in[21];
    const float *mo = (const float*)d_in[22], *vo = (const float*)d_in[23];
    const float* Wo2 = (const float*)d_in[24];
    const float* bo2 = (const float*)d_in[25];

    __half *p1h, *p2h, *p3h, *w1t, *w2t, *w3t;
    float *f3, *bn;
    cudaGetSymbolAddress((void**)&p1h, g_p1h);
    cudaGetSymbolAddress((void**)&p2h, g_p2h);
    cudaGetSymbolAddress((void**)&p3h, g_p3h);
    cudaGetSymbolAddress((void**)&f3,  g_f3);
    cudaGetSymbolAddress((void**)&w1t, g_w1t); cudaGetSymbolAddress((void**)&w2t, g_w2t);
    cudaGetSymbolAddress((void**)&w3t, g_w3t);
    cudaGetSymbolAddress((void**)&bn,  g_bn);

    // smem: 2KB sc + 2*ASZ (A dbl) + 4*BSTRIDE (B quad)
    const int smem1 = 2048 + 2 * 23552 + 4 * 256 * 128;   // 180224 (big-acc, 1 CTA/SM)
    const int smem2 = 2048 + 2 * 23552 + 4 * 64  * 128;   // 81920
    const int smem3 = 2048 + 2 * 41984 + 4 * 32  * 128;   // 102400
    cudaFuncSetAttribute(conv_mma<256, 256, 256, 128, 2, 4, false, 1>,
                         cudaFuncAttributeMaxDynamicSharedMemorySize, smem1);
    cudaFuncSetAttribute(conv_mma<256, 64, 64, 128, 4, 2, false, 2>,
                         cudaFuncAttributeMaxDynamicSharedMemorySize, smem2);
    cudaFuncSetAttribute(conv_mma<64, 32, 32, 256, 8, 1, true, 2>,
                         cudaFuncAttributeMaxDynamicSharedMemorySize, smem3);

    // launch order keeps conv1 in the ncu-profiled slot (4th)
    convert_input<<<dim3(DHW_ / 64, 4, 2), 256>>>(fea, p1h);

    const int EALL = 108 * 256 * 64 + 108 * 64 * 64 + 27 * 32 * 64;
    prep_all<<<(EALL + 255) / 256, 256>>>(W1, W2, W3, w1t, w2t, w3t);

    bn_fold<<<1, 384>>>(g1, b1, m1, v1, g2, b2, m2, v2, g3, b3, m3, v3);

    // conv1: full N=256 per CTA (MTI=4, NTI=8, 128-reg acc) -> grid.x = 8
    conv_mma<256, 256, 256, 128, 2, 4, false, 1>
        <<<dim3(8, 64, 2), 256, smem1>>>(p1h, w1t, bn, bn + 256, p2h, nullptr);
    // conv2: M=128 (R11-proven) -> grid.x = 8
    conv_mma<256, 64, 64, 128, 4, 2, false, 2>
        <<<dim3(8, 64, 2), 256, smem2>>>(p2h, w2t, bn + 512, bn + 576, p3h, nullptr);
    // conv3: M=256 -> grid.x = 4 (NT=27 odd: last pair single-tap)
    conv_mma<64, 32, 32, 256, 8, 1, true, 2>
        <<<dim3(4, 64, 2), 256, smem3>>>(p3h, w3t, bn + 640, bn + 672, nullptr, f3);

    int N = in_sizes[1] / 6;
    gather_mlp<<<(2 * N + 255) / 256, 256>>>(f3, grid_ind, xyz,
                                             Wo1, bo1, go, bo, mo, vo, Wo2, bo2,
                                             (float*)d_out, N);
}

// round 17
// speedup vs baseline: 1.0434x; 1.0434x over previous
#include <cuda_runtime.h>
#include <cuda_fp16.h>
#include <cstdint>

// Geometry (fixed): B=2, C0=256, D=64, H=64, W=16
#define D_   64
#define H_   64
#define W_   16
#define DHW_ 65536
#define DP_  66
#define HP_  66
#define WP_  18
#define PPOS_ (DP_*HP_*WP_)        // 78408 padded positions per batch

// ---------------------------------------------------------------------------
// Device scratch (zero-initialized at load; halos never written -> stay zero)
// ---------------------------------------------------------------------------
__device__ __half g_p1h[2 * PPOS_ * 256];       // conv1 input
__device__ __half g_p2h[2 * PPOS_ * 256];       // conv1 out / conv2 in
__device__ __half g_p3h[2 * PPOS_ * 64];        // conv2 out / conv3 in
__device__ float  g_f3 [2 * DHW_ * 32];
__device__ __half g_w1t[108 * 256 * 64];        // pre-swizzled hi-only tiles
__device__ __half g_w2t[108 * 64  * 64];
__device__ __half g_w3t[ 27 * 32  * 64];
__device__ float  g_bn [2 * (256 + 64 + 32)];

#define SWZ128(o) ((o) ^ (((o) >> 3) & 0x70))

__device__ __forceinline__ uint32_t smem_to_u32(const void* p) {
    uint32_t a;
    asm("{ .reg .u64 t; cvta.to.shared.u64 t, %1; cvt.u32.u64 %0, t; }" : "=r"(a) : "l"(p));
    return a;
}
__device__ __forceinline__ void ldm_x4(uint32_t* r, uint32_t addr) {
    asm volatile("ldmatrix.sync.aligned.m8n8.x4.shared.b16 {%0,%1,%2,%3}, [%4];"
                 : "=r"(r[0]), "=r"(r[1]), "=r"(r[2]), "=r"(r[3]) : "r"(addr));
}
__device__ __forceinline__ void mma16816(float* c, const uint32_t* a, const uint32_t* b) {
    asm volatile("mma.sync.aligned.m16n8k16.row.col.f32.f16.f16.f32 "
                 "{%0,%1,%2,%3}, {%4,%5,%6,%7}, {%8,%9}, {%0,%1,%2,%3};"
                 : "+f"(c[0]), "+f"(c[1]), "+f"(c[2]), "+f"(c[3])
                 : "r"(a[0]), "r"(a[1]), "r"(a[2]), "r"(a[3]), "r"(b[0]), "r"(b[1]));
}
__device__ __forceinline__ void cpasync16(uint32_t dst, const void* src) {
    asm volatile("cp.async.cg.shared.global [%0], [%1], 16;" :: "r"(dst), "l"(src));
}
#define CP_COMMIT() asm volatile("cp.async.commit_group;" ::: "memory")
#define CP_WAIT0()  asm volatile("cp.async.wait_group 0;" ::: "memory")

// ---------------------------------------------------------------------------
// fea (NCDHW fp32) -> padded channels-last fp16 (transpose in smem),
// packed 2-channel (u32) stores
// ---------------------------------------------------------------------------
__global__ void convert_input(const float* __restrict__ fea,
                              __half* __restrict__ ph) {
    __shared__ float tile[64][65];
    int pos0 = blockIdx.x * 64;
    int cb   = blockIdx.y * 64;
    int b    = blockIdx.z;
    int x = threadIdx.x & 63, y = threadIdx.x >> 6;
    const float* src = fea + (size_t)b * 256 * DHW_;
    #pragma unroll
    for (int r = 0; r < 64; r += 4)
        tile[r + y][x] = src[(size_t)(cb + r + y) * DHW_ + pos0 + x];
    __syncthreads();
    #pragma unroll
    for (int i = threadIdx.x; i < 64 * 32; i += 256) {
        int p  = i >> 5;
        int cp = i & 31;
        int pos = pos0 + p;
        int d = pos >> 10, h = (pos >> 4) & 63, w = pos & 15;
        size_t pa = ((((size_t)b * DP_ + d + 1) * HP_ + h + 1) * WP_ + w + 1) * 256 + cb + cp * 2;
        __half h0 = __float2half_rn(tile[cp * 2 + 0][p]);
        __half h1 = __float2half_rn(tile[cp * 2 + 1][p]);
        *(uint32_t*)(ph + pa) =
            (uint32_t)__half_as_ushort(h0) | ((uint32_t)__half_as_ushort(h1) << 16);
    }
}

// ---------------------------------------------------------------------------
// Weight prep (all three layers, one launch): fp32 -> pre-swizzled SW128
// K-major fp16 tiles, hi-only, layout [iter][COUT*64]
// ---------------------------------------------------------------------------
__device__ __forceinline__ void prep_one(const float* __restrict__ Wsrc,
                                         __half* __restrict__ out,
                                         int idx, int CIN, int COUT) {
    int it = idx / (COUT * 64);
    int r  = idx % (COUT * 64);
    int co = r / 64, kk = r % 64;
    int ch = CIN / 64;
    int t  = it / ch, cc = it % ch;
    int ci = cc * 64 + kk;
    float v = Wsrc[((size_t)co * CIN + ci) * 27 + t];
    int so = SWZ128(co * 128 + kk * 2);
    out[(size_t)it * (COUT * 64) + so / 2] = __float2half_rn(v);
}
__global__ void prep_all(const float* __restrict__ W1, const float* __restrict__ W2,
                         const float* __restrict__ W3,
                         __half* __restrict__ w1t, __half* __restrict__ w2t,
                         __half* __restrict__ w3t) {
    const int E1 = 108 * 256 * 64, E2 = 108 * 64 * 64, E3 = 27 * 32 * 64;
    int idx = blockIdx.x * blockDim.x + threadIdx.x;
    if (idx < E1) prep_one(W1, w1t, idx, 256, 256);
    else if (idx < E1 + E2) prep_one(W2, w2t, idx - E1, 256, 64);
    else if (idx < E1 + E2 + E3) prep_one(W3, w3t, idx - E1 - E2, 64, 32);
}

// ---------------------------------------------------------------------------
// Fold BN params for all three conv layers
// ---------------------------------------------------------------------------
__global__ void bn_fold(const float* g1, const float* b1, const float* m1, const float* v1,
                        const float* g2, const float* b2, const float* m2, const float* v2,
                        const float* g3, const float* b3, const float* m3, const float* v3) {
    int t = threadIdx.x;
    if (t < 256) {
        float sc = g1[t] * rsqrtf(v1[t] + 1e-5f);
        g_bn[t] = sc; g_bn[256 + t] = b1[t] - m1[t] * sc;
    } else if (t < 320) {
        int c = t - 256;
        float sc = g2[c] * rsqrtf(v2[c] + 1e-5f);
        g_bn[512 + c] = sc; g_bn[576 + c] = b2[c] - m2[c] * sc;
    } else if (t < 352) {
        int c = t - 320;
        float sc = g3[c] * rsqrtf(v3[c] + 1e-5f);
        g_bn[640 + c] = sc; g_bn[672 + c] = b3[c] - m3[c] * sc;
    }
}

// ---------------------------------------------------------------------------
// HMMA implicit-GEMM conv.
// PAIR=1 (R11-proven): B quad-buffered, two taps per barrier, prefetch +2/+3.
// PAIR=0 (R8-proven):  B double-buffered, one tap per barrier, prefetch +1.
// A halo double-buffered across phases in both modes.
// ---------------------------------------------------------------------------
template<int CIN, int COUTF, int NLOC, int MTILE, int MWARPS, int NWARPS,
         bool F32OUT, int PAIR>
__global__ __launch_bounds__(256, 2)
void conv_mma(const __half* __restrict__ pin_h,
              const __half* __restrict__ wt,
              const float* __restrict__ scv, const float* __restrict__ shv,
              __half* __restrict__ pout_h,
              float* __restrict__ foutp) {
    extern __shared__ __align__(1024) char smem[];
    constexpr int CHUNKS  = CIN / 64;
    constexpr int NPH     = 3 * CHUNKS;
    constexpr int NT      = NPH * 9;
    constexpr int HROWS   = MTILE / 16;
    constexpr int HT      = 64 / HROWS;
    constexpr int AROWS   = (HROWS + 2) * 18;
    constexpr int ASZ     = ((AROWS * 128 + 1023) / 1024) * 1024;
    constexpr int AOFF    = 2048;
    constexpr int BBASE   = AOFF + 2 * ASZ;
    constexpr int BSTRIDE = NLOC * 128;
    constexpr int BMASK   = PAIR ? 3 : 1;
    constexpr int WM = MTILE / MWARPS;
    constexpr int WN = NLOC / NWARPS;
    constexpr int MTI = WM / 16;
    constexpr int NTI = WN / 8;

    const uint32_t sbase = smem_to_u32(smem);
    const int tid = threadIdx.x, wid = tid >> 5, l = tid & 31;
    const int ntile = blockIdx.x / HT;
    const int h0 = (blockIdx.x % HT) * HROWS;
    const int d  = blockIdx.y;
    const int b  = blockIdx.z;
    const int n0 = ntile * NLOC;
    const int wm = wid % MWARPS, wn = wid / MWARPS;
    float* scp = (float*)smem;

    for (int c = tid; c < NLOC; c += 256) {
        scp[c] = scv[n0 + c];
        scp[NLOC + c] = shv[n0 + c];
    }

    float acc[MTI][NTI][4];
    #pragma unroll
    for (int i = 0; i < MTI; i++)
        #pragma unroll
        for (int j = 0; j < NTI; j++)
            #pragma unroll
            for (int q = 0; q < 4; q++) acc[i][j][q] = 0.f;

    const int arow = ((l >> 3) & 1) * 8 + (l & 7);
    const int akh  = (l >> 4);
    const int brow = (l >> 4) * 8 + (l & 7);
    const int bkh  = (l >> 3) & 1;
    const int mbase = wm * WM + arow;
    const int mh0 = mbase >> 4;
    const int mw  = mbase & 15;

    auto stageA = [&](int p2) {
        const int kd2 = p2 / CHUNKS, cc2 = p2 % CHUNKS;
        const size_t gb = (((size_t)b * DP_ + d + kd2) * HP_ + h0) * WP_;
        const uint32_t abuf = sbase + AOFF + (p2 & 1) * ASZ;
        #pragma unroll 1
        for (int i = tid; i < AROWS * 8; i += 256) {
            int r = i >> 3, c8 = i & 7;
            int hz = r / 18, wz = r - hz * 18;
            size_t ga = (gb + (size_t)hz * WP_ + wz) * CIN + cc2 * 64 + c8 * 8;
            cpasync16(abuf + SWZ128(r * 128 + c8 * 16), pin_h + ga);
        }
    };
    auto stageB = [&](int gt2) {
        const int p2 = gt2 / 9, tp2 = gt2 - p2 * 9;
        const int kd2 = p2 / CHUNKS, cc2 = p2 % CHUNKS;
        const int iter = (kd2 * 9 + tp2) * CHUNKS + cc2;
        const char* whi = (const char*)(wt + (size_t)iter * (COUTF * 64) + n0 * 64);
        const uint32_t dst = sbase + BBASE + (gt2 & BMASK) * BSTRIDE;
        #pragma unroll 1
        for (int i = tid; i < NLOC * 8; i += 256)
            cpasync16(dst + i * 16, whi + i * 16);
    };
    auto compute_tap = [&](int gt) {
        const int phs = gt / 9, tap = gt - phs * 9;
        const uint32_t abase = sbase + AOFF + (phs & 1) * ASZ;
        const uint32_t bbuf  = sbase + BBASE + (gt & BMASK) * BSTRIDE;
        const int kh = tap / 3, kw = tap - kh * 3;
        const int rb = (mh0 + kh) * 18 + mw + kw;
        #pragma unroll
        for (int ks = 0; ks < 4; ks++) {
            uint32_t ah[MTI][4];
            #pragma unroll
            for (int i = 0; i < MTI; i++) {
                uint32_t so = SWZ128((uint32_t)(rb + i * 18) * 128 + (ks * 2 + akh) * 16);
                ldm_x4(ah[i], abase + so);
            }
            uint32_t bh[NTI / 2][4];
            #pragma unroll
            for (int jp = 0; jp < NTI / 2; jp++) {
                uint32_t so = SWZ128((uint32_t)(wn * WN + jp * 16 + brow) * 128 + (ks * 2 + bkh) * 16);
                ldm_x4(bh[jp], bbuf + so);
            }
            #pragma unroll
            for (int i = 0; i < MTI; i++)
                #pragma unroll
                for (int jp = 0; jp < NTI / 2; jp++) {
                    mma16816(acc[i][2*jp],   ah[i], &bh[jp][0]);
                    mma16816(acc[i][2*jp+1], ah[i], &bh[jp][2]);
                }
        }
    };

    if (PAIR) {
        // R11 schedule: pair-tap, quad-B
        stageA(0);
        stageB(0);
        stageB(1);
        CP_COMMIT();
        #pragma unroll 1
        for (int gs = 0; gs < (NT + 1) / 2; ++gs) {
            const int gt0 = 2 * gs;
            CP_WAIT0();
            __syncthreads();
            if (gt0 + 2 < NT) stageB(gt0 + 2);
            if (gt0 + 3 < NT) stageB(gt0 + 3);
            {
                const int m9 = gt0 % 9, ph0 = gt0 / 9;
                if ((m9 == 5 || m9 == 6) && ph0 + 1 < NPH) stageA(ph0 + 1);
            }
            CP_COMMIT();
            compute_tap(gt0);
            if (gt0 + 1 < NT) compute_tap(gt0 + 1);
        }
    } else {
        // R8 schedule: single-tap, double-B
        stageA(0);
        stageB(0);
        CP_COMMIT();
        #pragma unroll 1
        for (int gt = 0; gt < NT; ++gt) {
            CP_WAIT0();
            __syncthreads();
            if (gt + 1 < NT) stageB(gt + 1);
            {
                const int m9 = gt % 9, ph0 = gt / 9;
                if (m9 == 5 && ph0 + 1 < NPH) stageA(ph0 + 1);
            }
            CP_COMMIT();
            compute_tap(gt);
        }
    }

    // ---- epilogue: BN + LeakyReLU, write channels-last ----
    #pragma unroll
    for (int i = 0; i < MTI; i++) {
        #pragma unroll
        for (int j = 0; j < NTI; j++) {
            int nl = wn * WN + j * 8 + (l & 3) * 2;
            int co = n0 + nl;
            float s0 = scp[nl],     h0c = scp[NLOC + nl];
            float s1 = scp[nl + 1], h1c = scp[NLOC + nl + 1];
            #pragma unroll
            for (int rh = 0; rh < 2; rh++) {
                int m  = wm * WM + i * 16 + (l >> 2) + rh * 8;
                int hh = h0 + (m >> 4), ww = m & 15;
                float y0 = acc[i][j][rh * 2 + 0] * s0 + h0c;
                float y1 = acc[i][j][rh * 2 + 1] * s1 + h1c;
                y0 = (y0 > 0.f) ? y0 : 0.01f * y0;
                y1 = (y1 > 0.f) ? y1 : 0.01f * y1;
                if (F32OUT) {
                    float* op = foutp + ((((size_t)b * D_ + d) * H_ + hh) * W_ + ww) * COUTF + co;
                    op[0] = y0; op[1] = y1;
                } else {
                    __half h0b = __float2half_rn(y0);
                    __half h1b = __float2half_rn(y1);
                    size_t pa = ((((size_t)b * DP_ + d + 1) * HP_ + hh + 1) * WP_ + ww + 1) * COUTF + co;
                    *(uint32_t*)(pout_h + pa) =
                        (uint32_t)__half_as_ushort(h0b) | ((uint32_t)__half_as_ushort(h1b) << 16);
                }
            }
        }
    }
}

// ---------------------------------------------------------------------------
// Gather (channels-last, 128B/point) + MLP 35->32 (BN,ReLU) -> 3
// ---------------------------------------------------------------------------
__global__ void gather_mlp(const float* __restrict__ f3,
                           const int* __restrict__ grid_ind,
                           const float* __restrict__ xyz,
                           const float* __restrict__ Wo1, const float* __restrict__ bo1,
                           const float* __restrict__ go,  const float* __restrict__ bo,
                           const float* __restrict__ mo,  const float* __restrict__ vo,
                           const float* __restrict__ Wo2, const float* __restrict__ bo2,
                           float* __restrict__ out, int N) {
    __shared__ float sW1[35 * 32];
    __shared__ float sb1[32], ssc[32], ssh[32];
    __shared__ float sW2[32 * 3], sb2[3];
    const int tid = threadIdx.x;
    for (int i = tid; i < 35 * 32; i += blockDim.x) sW1[i] = Wo1[i];
    if (tid < 32) {
        float sc = go[tid] * rsqrtf(vo[tid] + 1e-5f);
        ssc[tid] = sc;
        ssh[tid] = bo[tid] - mo[tid] * sc;
        sb1[tid] = bo1[tid];
    }
    for (int i = tid; i < 96; i += blockDim.x) sW2[i] = Wo2[i];
    if (tid < 3) sb2[tid] = bo2[tid];
    __syncthreads();

    int idx = blockIdx.x * blockDim.x + tid;
    if (idx >= 2 * N) return;
    int b = idx / N;
    const int* gi = grid_ind + (size_t)idx * 3;
    int sp = (gi[0] * H_ + gi[1]) * W_ + gi[2];

    float xin[35];
    const float* fb = f3 + ((size_t)b * DHW_ + sp) * 32;
    #pragma unroll
    for (int c = 0; c < 32; c++) xin[c] = fb[c];
    const float* xp = xyz + (size_t)idx * 3;
    xin[32] = xp[0]; xin[33] = xp[1]; xin[34] = xp[2];

    float hreg[32];
    #pragma unroll
    for (int j = 0; j < 32; j++) hreg[j] = sb1[j];
    #pragma unroll 5
    for (int k = 0; k < 35; k++) {
        float xk = xin[k];
        #pragma unroll
        for (int j = 0; j < 32; j++) hreg[j] = fmaf(xk, sW1[k * 32 + j], hreg[j]);
    }
    #pragma unroll
    for (int j = 0; j < 32; j++) {
        float y = hreg[j] * ssc[j] + ssh[j];
        hreg[j] = (y > 0.f) ? y : 0.f;
    }
    float o0 = sb2[0], o1 = sb2[1], o2 = sb2[2];
    #pragma unroll
    for (int j = 0; j < 32; j++) {
        o0 = fmaf(hreg[j], sW2[j * 3 + 0], o0);
        o1 = fmaf(hreg[j], sW2[j * 3 + 1], o1);
        o2 = fmaf(hreg[j], sW2[j * 3 + 2], o2);
    }
    float* op = out + (size_t)idx * 3;
    op[0] = o0; op[1] = o1; op[2] = o2;
}

extern "C" void kernel_launch(void* const* d_in, const int* in_sizes, int n_in,
                              void* d_out, int out_size) {
    const float* fea      = (const float*)d_in[0];
    const int*   grid_ind = (const int*)  d_in[1];
    const float* xyz      = (const float*)d_in[2];
    const float* W1 = (const float*)d_in[3];
    const float *g1 = (const float*)d_in[4], *b1 = (const float*)d_in[5];
    const float *m1 = (const float*)d_in[6], *v1 = (const float*)d_in[7];
    const float* W2 = (const float*)d_in[8];
    const float *g2 = (const float*)d_in[9],  *b2 = (const float*)d_in[10];
    const float *m2 = (const float*)d_in[11], *v2 = (const float*)d_in[12];
    const float* W3 = (const float*)d_in[13];
    const float *g3 = (const float*)d_in[14], *b3 = (const float*)d_in[15];
    const float *m3 = (const float*)d_in[16], *v3 = (const float*)d_in[17];
    const float* Wo1 = (const float*)d_in[18];
    const float* bo1 = (const float*)d_in[19];
    const float *go = (const float*)d_in[20], *bo = (const float*)d_in[21];
    const float *mo = (const float*)d_in[22], *vo = (const float*)d_in[23];
    const float* Wo2 = (const float*)d_in[24];
    const float* bo2 = (const float*)d_in[25];

    __half *p1h, *p2h, *p3h, *w1t, *w2t, *w3t;
    float *f3, *bn;
    cudaGetSymbolAddress((void**)&p1h, g_p1h);
    cudaGetSymbolAddress((void**)&p2h, g_p2h);
    cudaGetSymbolAddress((void**)&p3h, g_p3h);
    cudaGetSymbolAddress((void**)&f3,  g_f3);
    cudaGetSymbolAddress((void**)&w1t, g_w1t); cudaGetSymbolAddress((void**)&w2t, g_w2t);
    cudaGetSymbolAddress((void**)&w3t, g_w3t);
    cudaGetSymbolAddress((void**)&bn,  g_bn);

    const int smem1 = 2048 + 2 * 23552 + 4 * 128 * 128;   // 114688 (pair-tap)
    const int smem2 = 2048 + 2 * 41984 + 2 * 64  * 128;   // 102400 (single-tap, M=256)
    const int smem3 = 2048 + 2 * 41984 + 4 * 32  * 128;   // 102400 (pair-tap, M=256)
    cudaFuncSetAttribute(conv_mma<256, 256, 128, 128, 2, 4, false, 1>,
                         cudaFuncAttributeMaxDynamicSharedMemorySize, smem1);
    cudaFuncSetAttribute(conv_mma<256, 64, 64, 256, 4, 2, false, 0>,
                         cudaFuncAttributeMaxDynamicSharedMemorySize, smem2);
    cudaFuncSetAttribute(conv_mma<64, 32, 32, 256, 8, 1, true, 1>,
                         cudaFuncAttributeMaxDynamicSharedMemorySize, smem3);

    // launch order keeps conv1 in the ncu-profiled slot (4th)
    convert_input<<<dim3(DHW_ / 64, 4, 2), 256>>>(fea, p1h);

    const int EALL = 108 * 256 * 64 + 108 * 64 * 64 + 27 * 32 * 64;
    prep_all<<<(EALL + 255) / 256, 256>>>(W1, W2, W3, w1t, w2t, w3t);

    bn_fold<<<1, 384>>>(g1, b1, m1, v1, g2, b2, m2, v2, g3, b3, m3, v3);

    // conv1: R11-proven config (N split into 2 tiles) -> grid.x = 16
    conv_mma<256, 256, 128, 128, 2, 4, false, 1>
        <<<dim3(16, 64, 2), 256, smem1>>>(p1h, w1t, bn, bn + 256, p2h, nullptr);
    // conv2: M=256, ratio 0.375, single-tap schedule -> grid.x = 4
    conv_mma<256, 64, 64, 256, 4, 2, false, 0>
        <<<dim3(4, 64, 2), 256, smem2>>>(p2h, w2t, bn + 512, bn + 576, p3h, nullptr);
    // conv3: M=256 pair-tap (NT=27 odd: last pair single-tap) -> grid.x = 4
    conv_mma<64, 32, 32, 256, 8, 1, true, 1>
        <<<dim3(4, 64, 2), 256, smem3>>>(p3h, w3t, bn + 640, bn + 672, nullptr, f3);

    int N = in_sizes[1] / 6;
    gather_mlp<<<(2 * N + 255) / 256, 256>>>(f3, grid_ind, xyz,
                                             Wo1, bo1, go, bo, mo, vo, Wo2, bo2,
                                             (float*)d_out, N);
}